// round 4
// baseline (speedup 1.0000x reference)
#include <cuda_runtime.h>
#include <math.h>

#define NA 48
#define NB 24
#define DIM 286
#define NBATCH 256
#define NMU 6
#define L5OFF 165

// Scratch (static device globals; no allocation)
__device__ float g_c[NA * NMU];                // cos-like per (x, mu)
__device__ float g_s[NA * NMU];                // sin-like per (x, mu)
__device__ float g_act;                        // normalize2mom constant for tanh
__device__ float g_part[48];                   // partials for activation integral
__device__ float g_Q[NBATCH * 36 * 4 * NB];    // Q forms [b][mn][c][y]

__constant__ int c_off[6] = {0, 1, 10, 35, 84, 165};

// fast exact-enough tanh: 1 - 2/(e^{2x}+1)   (rel err ~1e-6, robust at +-inf)
__device__ __forceinline__ float ftanh(float x) {
    float e = __expf(2.0f * x);
    return 1.0f - 2.0f / (e + 1.0f);
}

// ---------------------------------------------------------------------------
// ACT_CST integral: trapz of tanh(x)^2 * N(0,1) over [-12,12], 100001 pts
// ---------------------------------------------------------------------------
__global__ void act_kernel() {
    int tid = blockIdx.x * blockDim.x + threadIdx.x;  // 48*256 = 12288
    float sum = 0.f;
    for (int i = tid; i <= 100000; i += 12288) {
        float x = -12.f + (float)i * 2.4e-4f;
        float t = tanhf(x);
        float p = __expf(-0.5f * x * x);
        sum += t * t * p;
    }
    for (int o = 16; o; o >>= 1) sum += __shfl_down_sync(0xffffffffu, sum, o);
    __shared__ float ws[8];
    int w = threadIdx.x >> 5;
    if ((threadIdx.x & 31) == 0) ws[w] = sum;
    __syncthreads();
    if (threadIdx.x == 0) {
        float b = 0.f;
        for (int i = 0; i < 8; i++) b += ws[i];
        g_part[blockIdx.x] = b;
    }
}

// ---------------------------------------------------------------------------
// Prep: per-sector 2x2 alpha-rotation (c,s) from the l=5 block of D:
// Ra5[x] = D5[x,0,0] * D5[0,0,0]^T / 11  (Rb orthogonal, Ra(0)=I)
// ---------------------------------------------------------------------------
__global__ void prep_kernel(const float* __restrict__ D) {
    int t = threadIdx.x;
    if (t < NA * NMU) {
        int x = t / NMU, mu = t % NMU;
        int p0 = 5 - mu, p1 = 5 + mu;
        const float* X = D + (size_t)x * NB * NA * DIM + L5OFF;
        const float* Z = D + L5OFF;
        float a00 = 0.f, a01 = 0.f, a10 = 0.f, a11 = 0.f;
        for (int k = 0; k < 11; k++) {
            float xp0 = X[p0 * 11 + k], xp1 = X[p1 * 11 + k];
            float zp0 = Z[p0 * 11 + k], zp1 = Z[p1 * 11 + k];
            a00 += xp0 * zp0; a01 += xp0 * zp1;
            a10 += xp1 * zp0; a11 += xp1 * zp1;
        }
        const float inv11 = 1.f / 11.f;
        g_c[t] = 0.5f * (a00 + a11) * inv11;
        g_s[t] = 0.5f * (a01 - a10) * inv11;
    }
    if (t == 0) {
        float tot = 0.f;
        for (int i = 0; i < 48; i++) tot += g_part[i];
        float I = tot * 2.4e-4f * 0.3989422804014327f;
        g_act = 1.0f / sqrtf(I);
    }
}

// ---------------------------------------------------------------------------
// Main: one CTA per (batch b, beta index y). Produces Q forms into g_Q.
// ---------------------------------------------------------------------------
__global__ __launch_bounds__(256) void so3_main(const float* __restrict__ feat,
                                                const float* __restrict__ D,
                                                const float* __restrict__ qw) {
    const int b = blockIdx.x / NB;
    const int y = blockIdx.x % NB;
    const int t = threadIdx.x;

    __shared__ float sF[DIM];
    __shared__ float sB[DIM];
    __shared__ float4 strig4[NA * 3];               // [x]: 12 floats (c,s)x6mu
    __shared__ __align__(16) float2 strigT[NMU][NA + 2];  // [mu][x], padded rows
    __shared__ float4 sP4[36];                      // (P00,P01,P10,P11)
    __shared__ __align__(16) float2 sT2[NMU][NA];   // (t0,t1)
    __shared__ float sG[NA][NA + 1];
    __shared__ float2 sU2[NMU][NA + 1];             // (u0,u1)

    float* strig = (float*)strig4;

    for (int i = t; i < DIM; i += 256) {
        sF[i] = feat[b * DIM + i];
        sB[i] = D[(size_t)y * NA * DIM + i];  // D[0][y][0][i]
    }
    for (int i = t; i < NA * NMU; i += 256) {
        int x = i / NMU, mu = i % NMU;
        float c = g_c[i], s = g_s[i];
        strig[x * 12 + mu * 2 + 0] = c;
        strig[x * 12 + mu * 2 + 1] = s;
        strigT[mu][x] = make_float2(c, s);
    }
    __syncthreads();

    // --- P forms (160 threads = 5 full warps; 4-way l-split + shfl) --------
    if (t < 160) {
        int g = t >> 2, sub = t & 3;
        bool valid = g < 36;
        int mu = valid ? g / 6 : 0, nu = valid ? g % 6 : 0;
        float P00 = 0.f, P01 = 0.f, P10 = 0.f, P11 = 0.f;
        if (valid) {
            int l0 = mu > nu ? mu : nu;
#pragma unroll
            for (int li = 0; li < 2; li++) {
                int l = l0 + sub + li * 4;
                if (l <= 5) {
                    int dl = 2 * l + 1, off = c_off[l];
                    int r0 = l - mu, r1 = l + mu, q0 = l - nu, q1 = l + nu;
                    float F00 = sF[off + r0 * dl + q0], F01 = sF[off + r0 * dl + q1];
                    float F10 = sF[off + r1 * dl + q0], F11 = sF[off + r1 * dl + q1];
                    float B00 = sB[off + r0 * dl + q0], B01 = sB[off + r0 * dl + q1];
                    float B10 = sB[off + r1 * dl + q0], B11 = sB[off + r1 * dl + q1];
                    if (mu == 0) { F10 = F11 = 0.f; B10 = B11 = 0.f; }
                    if (nu == 0) { F01 = F11 = 0.f; B01 = B11 = 0.f; }
                    P00 +=  F00 * B00 + F01 * B01 + F10 * B10 + F11 * B11;
                    P01 += -F00 * B01 + F01 * B00 - F10 * B11 + F11 * B10;
                    P10 +=  F00 * B10 + F01 * B11 - F10 * B00 - F11 * B01;
                    P11 += -F00 * B11 + F01 * B10 + F10 * B01 - F11 * B00;
                }
            }
        }
#define RED4(v) v += __shfl_xor_sync(0xffffffffu, v, 1); v += __shfl_xor_sync(0xffffffffu, v, 2)
        RED4(P00); RED4(P01); RED4(P10); RED4(P11);
        if (valid && sub == 0) sP4[g] = make_float4(P00, P01, P10, P11);
    }
    __syncthreads();

    // --- T stage: contract nu with z-trig ---------------------------------
    for (int i = t; i < NMU * NA; i += 256) {
        int mu = i / NA, z = i % NA;
        float t0 = 0.f, t1 = 0.f;
#pragma unroll
        for (int nu = 0; nu < NMU; nu++) {
            float4 P = sP4[mu * 6 + nu];
            float2 cs = strigT[nu][z];
            t0 += P.x * cs.x + P.y * cs.y;
            t1 += P.z * cs.x + P.w * cs.y;
        }
        sT2[mu][z] = make_float2(t0, t1);
    }
    __syncthreads();

    // --- synthesis + activation (3x x 4z register tiles, 192 threads) -----
    if (t < 192) {
        const float inv_s = 1.f / sqrtf(286.f);
        const float actq = g_act * qw[y];
        int xt = t / 12, zt = t % 12;   // 16 x-tiles of 3, 12 z-tiles of 4
        int x0 = xt * 3, z0 = zt * 4;
        float a[3][4] = {};
#pragma unroll
        for (int mu = 0; mu < NMU; mu++) {
            float2 c0 = *(const float2*)(strig + (x0 + 0) * 12 + mu * 2);
            float2 c1 = *(const float2*)(strig + (x0 + 1) * 12 + mu * 2);
            float2 c2 = *(const float2*)(strig + (x0 + 2) * 12 + mu * 2);
            float4 Ta = *(const float4*)&sT2[mu][z0];      // z0, z0+1
            float4 Tb = *(const float4*)&sT2[mu][z0 + 2];  // z0+2, z0+3
            a[0][0] += c0.x * Ta.x + c0.y * Ta.y;
            a[0][1] += c0.x * Ta.z + c0.y * Ta.w;
            a[0][2] += c0.x * Tb.x + c0.y * Tb.y;
            a[0][3] += c0.x * Tb.z + c0.y * Tb.w;
            a[1][0] += c1.x * Ta.x + c1.y * Ta.y;
            a[1][1] += c1.x * Ta.z + c1.y * Ta.w;
            a[1][2] += c1.x * Tb.x + c1.y * Tb.y;
            a[1][3] += c1.x * Tb.z + c1.y * Tb.w;
            a[2][0] += c2.x * Ta.x + c2.y * Ta.y;
            a[2][1] += c2.x * Ta.z + c2.y * Ta.w;
            a[2][2] += c2.x * Tb.x + c2.y * Tb.y;
            a[2][3] += c2.x * Tb.z + c2.y * Tb.w;
        }
#pragma unroll
        for (int i = 0; i < 3; i++)
#pragma unroll
            for (int j = 0; j < 4; j++)
                sG[x0 + i][z0 + j] = actq * ftanh(a[i][j] * inv_s);
    }
    __syncthreads();

    // --- U stage: contract x with trig; 4 lanes split x, shuffle-reduce ---
    if (t < 192) {
        int z = t >> 2, xg = t & 3;
        float u0 = 0.f, u1 = 0.f, u2 = 0.f, u3 = 0.f, u4 = 0.f, u5 = 0.f;
        float u6 = 0.f, u7 = 0.f, u8 = 0.f, u9 = 0.f, u10 = 0.f, u11 = 0.f;
#pragma unroll
        for (int k = 0; k < 12; k++) {
            int x = xg * 12 + k;
            float g = sG[x][z];
            float4 ta = strig4[x * 3 + 0];
            float4 tb = strig4[x * 3 + 1];
            float4 tc = strig4[x * 3 + 2];
            u0 += ta.x * g;  u1 += ta.y * g;  u2 += ta.z * g;  u3 += ta.w * g;
            u4 += tb.x * g;  u5 += tb.y * g;  u6 += tb.z * g;  u7 += tb.w * g;
            u8 += tc.x * g;  u9 += tc.y * g;  u10 += tc.z * g; u11 += tc.w * g;
        }
        RED4(u0); RED4(u1); RED4(u2); RED4(u3); RED4(u4); RED4(u5);
        RED4(u6); RED4(u7); RED4(u8); RED4(u9); RED4(u10); RED4(u11);
        if (xg == 0) {
            sU2[0][z] = make_float2(u0, u1);
            sU2[1][z] = make_float2(u2, u3);
            sU2[2][z] = make_float2(u4, u5);
            sU2[3][z] = make_float2(u6, u7);
            sU2[4][z] = make_float2(u8, u9);
            sU2[5][z] = make_float2(u10, u11);
        }
    }
    __syncthreads();

    // --- Q forms (160 threads; 4-way z-split + shfl) + transposed store ---
    if (t < 160) {
        int g = t >> 2, sub = t & 3;
        bool valid = g < 36;
        int mu = valid ? g / 6 : 0, nu = valid ? g % 6 : 0;
        float Q00 = 0.f, Q01 = 0.f, Q10 = 0.f, Q11 = 0.f;
        if (valid) {
#pragma unroll
            for (int k = 0; k < 12; k++) {
                int z = sub * 12 + k;
                float2 u = sU2[mu][z];
                float2 cs = strigT[nu][z];
                Q00 += u.x * cs.x; Q01 += u.x * cs.y;
                Q10 += u.y * cs.x; Q11 += u.y * cs.y;
            }
        }
        RED4(Q00); RED4(Q01); RED4(Q10); RED4(Q11);
#undef RED4
        if (valid && sub == 0) {
            int base = ((b * 36 + g) * 4) * NB + y;
            g_Q[base + 0 * NB] = Q00;
            g_Q[base + 1 * NB] = Q01;
            g_Q[base + 2 * NB] = Q10;
            g_Q[base + 3 * NB] = Q11;
        }
    }
}

// ---------------------------------------------------------------------------
// Scatter: pure-LDG, no smem, no barriers. One thread per output element.
//   out(r,q) = sum_y Q00 B(r,q) + sq Q01 B(r,qb) + sr Q10 B(rb,q) + sr sq Q11 B(rb,qb)
// B-slice (27KB) is L2/L1-hot (shared across all b); Q[b] slice is 13.8KB.
// ---------------------------------------------------------------------------
__global__ __launch_bounds__(288) void scatter_kernel(const float* __restrict__ D,
                                                      float* __restrict__ out) {
    const int b = blockIdx.x;
    const int t = threadIdx.x;
    if (t >= DIM) return;

    int l = 5;
    if (t < 165) l = 4;
    if (t < 84)  l = 3;
    if (t < 35)  l = 2;
    if (t < 10)  l = 1;
    if (t < 1)   l = 0;
    int off = c_off[l], dl = 2 * l + 1;
    int k = t - off;
    int r = k / dl, q = k - r * dl;
    int rb = 2 * l - r, qb = 2 * l - q;
    int mu = r < l ? l - r : r - l;
    int nu = q < l ? l - q : q - l;
    float sr_ = (r < l) ? 1.f : -1.f;
    float sq_ = (q > l) ? 1.f : -1.f;
    int i_rq = t;
    int i_rqb = off + r * dl + qb;
    int i_rbq = off + rb * dl + q;
    int i_rbqb = off + rb * dl + qb;

    const float* Qp = g_Q + ((size_t)(b * 36 + mu * 6 + nu)) * 4 * NB;
    float A0 = 0.f, A1 = 0.f, A2 = 0.f, A3 = 0.f;
#pragma unroll
    for (int yv = 0; yv < 6; yv++) {
        float4 q0 = *(const float4*)(Qp + 0 * NB + yv * 4);
        float4 q1 = *(const float4*)(Qp + 1 * NB + yv * 4);
        float4 q2 = *(const float4*)(Qp + 2 * NB + yv * 4);
        float4 q3 = *(const float4*)(Qp + 3 * NB + yv * 4);
        const float* B0 = D + (size_t)(yv * 4 + 0) * NA * DIM;
        const float* B1 = D + (size_t)(yv * 4 + 1) * NA * DIM;
        const float* B2 = D + (size_t)(yv * 4 + 2) * NA * DIM;
        const float* B3 = D + (size_t)(yv * 4 + 3) * NA * DIM;
        A0 += q0.x * B0[i_rq]  + q0.y * B1[i_rq]  + q0.z * B2[i_rq]  + q0.w * B3[i_rq];
        A1 += q1.x * B0[i_rqb] + q1.y * B1[i_rqb] + q1.z * B2[i_rqb] + q1.w * B3[i_rqb];
        A2 += q2.x * B0[i_rbq] + q2.y * B1[i_rbq] + q2.z * B2[i_rbq] + q2.w * B3[i_rbq];
        A3 += q3.x * B0[i_rbqb]+ q3.y * B1[i_rbqb]+ q3.z * B2[i_rbqb]+ q3.w * B3[i_rbqb];
    }
    float acc = A0 + sq_ * A1 + sr_ * (A2 + sq_ * A3);
    out[(size_t)b * DIM + t] = sqrtf(286.f) * acc;
}

extern "C" void kernel_launch(void* const* d_in, const int* in_sizes, int n_in,
                              void* d_out, int out_size) {
    const float* feat = (const float*)d_in[0];  // [256, 286]
    const float* D    = (const float*)d_in[1];  // [48, 24, 48, 286]
    const float* qw   = (const float*)d_in[2];  // [24]
    float* out        = (float*)d_out;          // [256, 286]

    act_kernel<<<48, 256>>>();
    prep_kernel<<<1, 512>>>(D);
    so3_main<<<NBATCH * NB, 256>>>(feat, D, qw);
    scatter_kernel<<<NBATCH, 288>>>(D, out);
}